// round 10
// baseline (speedup 1.0000x reference)
#include <cuda_runtime.h>
#include <cstddef>

// Problem shapes (fixed by setup_inputs): B=16, N=2048, S=12, SO=12, K=32
#define SDIM  12
#define KNEI  32
#define NNODE 2048
#define NBATCH 16
#define LRELU_ALPHA 0.5f

// One warp per (b, n). Lane k owns neighbor k (K == warp size).
//
//   u = W @ a[:SO]   (S,)      e_src[b,i] = input[b,i,:] . u
//   v = W @ a[SO:]   (S,)      e_dst[b,j] = input[b,j,:] . v
//   score = leaky_relu(e_src + e_dst, 0.5); softmax over the 32 gathered
//   neighbors; out[b,i,k,:] = att_k * input[b, idx[b,i,k], :]
//
// e_dst is recomputed from the gathered neighbor row (which we must load
// anyway for the output product) -> single kernel, no scratch, no N x N
// scores matrix.
__global__ __launch_bounds__(256, 8)
void clustering_attention_45286135169491_kernel(
    const float* __restrict__ input,   // (B, N, S)
    const float* __restrict__ W,       // (S, SO) row-major
    const float* __restrict__ a,       // (2*SO,)
    const int*   __restrict__ idx,     // (B, N, K)
    float*       __restrict__ out)     // (B, N, K, S)
{
    __shared__ float su[SDIM];
    __shared__ float sv[SDIM];

    const int tid = threadIdx.x;

    // threads 0..23 compute u (first 12) and v (last 12)
    if (tid < 2 * SDIM) {
        const int  s    = tid % SDIM;
        const bool isv  = (tid >= SDIM);
        const float* av = a + (isv ? SDIM : 0);
        float acc = 0.0f;
#pragma unroll
        for (int o = 0; o < SDIM; ++o)
            acc = fmaf(W[s * SDIM + o], av[o], acc);
        if (isv) sv[s] = acc; else su[s] = acc;
    }
    __syncthreads();

    const int warp = (blockIdx.x * blockDim.x + tid) >> 5;  // = b*N + n
    const int lane = tid & 31;
    if (warp >= NBATCH * NNODE) return;
    const int b = warp / NNODE;

    // --- e_src: lane 0 loads own row (3 x float4), dots with u, broadcasts ---
    float es = 0.0f;
    if (lane == 0) {
        const float4* row = reinterpret_cast<const float4*>(
            input + (size_t)warp * SDIM);
        float4 r0 = row[0], r1 = row[1], r2 = row[2];
        es = r0.x*su[0] + r0.y*su[1] + r0.z*su[2]  + r0.w*su[3]
           + r1.x*su[4] + r1.y*su[5] + r1.z*su[6]  + r1.w*su[7]
           + r2.x*su[8] + r2.y*su[9] + r2.z*su[10] + r2.w*su[11];
    }
    es = __shfl_sync(0xffffffffu, es, 0);

    // --- lane k: gather neighbor row, compute e_dst in-place ---
    const int nb = idx[(size_t)warp * KNEI + lane];
    const float4* nrow = reinterpret_cast<const float4*>(
        input + ((size_t)b * NNODE + (size_t)nb) * SDIM);
    const float4 n0 = nrow[0], n1 = nrow[1], n2 = nrow[2];

    const float ed =
          n0.x*sv[0] + n0.y*sv[1] + n0.z*sv[2]  + n0.w*sv[3]
        + n1.x*sv[4] + n1.y*sv[5] + n1.z*sv[6]  + n1.w*sv[7]
        + n2.x*sv[8] + n2.y*sv[9] + n2.z*sv[10] + n2.w*sv[11];

    float sc = es + ed;
    sc = (sc >= 0.0f) ? sc : LRELU_ALPHA * sc;

    // --- warp softmax over the 32 neighbors ---
    float m = sc;
#pragma unroll
    for (int off = 16; off > 0; off >>= 1)
        m = fmaxf(m, __shfl_xor_sync(0xffffffffu, m, off));
    const float p = __expf(sc - m);
    float sum = p;
#pragma unroll
    for (int off = 16; off > 0; off >>= 1)
        sum += __shfl_xor_sync(0xffffffffu, sum, off);
    const float att = p / sum;

    // --- write out[b,n,k,0..11] = att * neigh (3 x float4, 16B aligned) ---
    float4* orow = reinterpret_cast<float4*>(
        out + ((size_t)warp * KNEI + (size_t)lane) * SDIM);
    orow[0] = make_float4(att * n0.x, att * n0.y, att * n0.z, att * n0.w);
    orow[1] = make_float4(att * n1.x, att * n1.y, att * n1.z, att * n1.w);
    orow[2] = make_float4(att * n2.x, att * n2.y, att * n2.z, att * n2.w);
}

extern "C" void kernel_launch(void* const* d_in, const int* in_sizes, int n_in,
                              void* d_out, int out_size)
{
    // metadata order: fushed_features (unused), input_data, W, a, idx
    const float* input = (const float*)d_in[1];
    const float* W     = (const float*)d_in[2];
    const float* a     = (const float*)d_in[3];
    const int*   idx   = (const int*)d_in[4];
    float*       out   = (float*)d_out;

    const int total_warps = NBATCH * NNODE;           // 32768
    const int threads = 256;                          // 8 warps/block
    const int blocks  = (total_warps * 32 + threads - 1) / threads;  // 4096

    clustering_attention_45286135169491_kernel<<<blocks, threads>>>(
        input, W, a, idx, out);
}

// round 11
// speedup vs baseline: 1.2301x; 1.2301x over previous
#include <cuda_runtime.h>
#include <cstddef>

// Shapes fixed by setup_inputs: B=16, N=2048, S=12, SO=12, K=32
#define SDIM   12
#define KNEI   32
#define NNODE  2048
#define NBATCH 16
#define LALPHA 0.5f

// One warp per (b,n). Chunk-cooperative gather:
//   96 chunks = 32 neighbor rows x 3 float4. Instruction i, lane l loads
//   chunk c = i*32 + l  (row = c/3, part = c%3). Consecutive lanes hit the
//   same 128B line for chunks of one row -> ~13 lines/LDG instead of 32.
//   e_dst partials computed per chunk; 3 shuffles/row collect them; softmax
//   in row-space; att shuffled back to chunk holders; store offset of chunk
//   c is exactly 4c floats -> coalesced float4 stores.
__global__ __launch_bounds__(256)
void clustering_attention_45286135169491_kernel(
    const float* __restrict__ input,   // (B, N, S)
    const float* __restrict__ W,       // (S, SO) row-major
    const float* __restrict__ a,       // (2*SO,)
    const int*   __restrict__ idx,     // (B, N, K)
    float*       __restrict__ out)     // (B, N, K, S)
{
    __shared__ float4 suv[6];          // u = suv[0..2], v = suv[3..5]

    const int tid = threadIdx.x;

    // threads 0..23: u[s] = sum_o W[s,o]*a[o],  v[s] = sum_o W[s,o]*a[SO+o]
    if (tid < 2 * SDIM) {
        const int  s   = tid % SDIM;
        const bool isv = (tid >= SDIM);
        const float* av = a + (isv ? SDIM : 0);
        float acc = 0.0f;
#pragma unroll
        for (int o = 0; o < SDIM; ++o)
            acc = fmaf(W[s * SDIM + o], av[o], acc);
        reinterpret_cast<float*>(suv)[(isv ? SDIM : 0) + s] = acc;
    }
    __syncthreads();

    const unsigned FULL = 0xffffffffu;
    const int warp = (blockIdx.x * blockDim.x + tid) >> 5;   // = b*N + n
    const int lane = tid & 31;
    const int b    = warp >> 11;                             // N = 2048

    const float4 u0 = suv[0], u1 = suv[1], u2 = suv[2];
    const float4 v0 = suv[3], v1 = suv[4], v2 = suv[5];

    const float* inb = input + (size_t)b * (NNODE * SDIM);

    // e_src: uniform-address load of the query row by all lanes (broadcast)
    const float4* qrow = reinterpret_cast<const float4*>(
        input + (size_t)warp * SDIM);
    const float4 q0 = qrow[0], q1 = qrow[1], q2 = qrow[2];
    const float es =
          q0.x*u0.x + q0.y*u0.y + q0.z*u0.z + q0.w*u0.w
        + q1.x*u1.x + q1.y*u1.y + q1.z*u1.z + q1.w*u1.w
        + q2.x*u2.x + q2.y*u2.y + q2.z*u2.z + q2.w*u2.w;

    // lane k holds idx for neighbor k
    const int my_idx = idx[(size_t)warp * KNEI + lane];

    float4 ch[3];
    float  part[3];
#pragma unroll
    for (int i = 0; i < 3; ++i) {
        const int c = i * 32 + lane;
        const int r = c / 3;
        const int p = c - 3 * r;
        const int row = __shfl_sync(FULL, my_idx, r);
        ch[i] = *reinterpret_cast<const float4*>(inb + (size_t)row * SDIM + p * 4);
        const float4 vs = (p == 0) ? v0 : ((p == 1) ? v1 : v2);
        part[i] = ch[i].x*vs.x + ch[i].y*vs.y + ch[i].z*vs.z + ch[i].w*vs.w;
    }

    // e_dst for row r=lane: partials live at chunk positions 3r+t (t=0,1,2).
    // In phase t, source lane s provides part[(s - t) mod 3]; dest reads from
    // lane (3r + t) & 31.
    float ed = 0.0f;
#pragma unroll
    for (int t = 0; t < 3; ++t) {
        const int isrc = (lane - t + 3) % 3;
        const float sval = (isrc == 0) ? part[0] : ((isrc == 1) ? part[1] : part[2]);
        ed += __shfl_sync(FULL, sval, (3 * lane + t) & 31);
    }

    // leaky_relu + warp softmax (row-space: lane = neighbor index)
    float sc = es + ed;
    sc = (sc >= 0.0f) ? sc : LALPHA * sc;
    float m = sc;
#pragma unroll
    for (int off = 16; off > 0; off >>= 1)
        m = fmaxf(m, __shfl_xor_sync(FULL, m, off));
    const float pex = __expf(sc - m);
    float sum = pex;
#pragma unroll
    for (int off = 16; off > 0; off >>= 1)
        sum += __shfl_xor_sync(FULL, sum, off);
    const float att = pex / sum;

    // store: chunk c -> out float offset 4c within this warp's 1536B row
    float4* ob = reinterpret_cast<float4*>(out) + (size_t)warp * 96;
#pragma unroll
    for (int i = 0; i < 3; ++i) {
        const int c = i * 32 + lane;
        const int r = c / 3;
        const float ai = __shfl_sync(FULL, att, r);
        ob[c] = make_float4(ai * ch[i].x, ai * ch[i].y, ai * ch[i].z, ai * ch[i].w);
    }
}

extern "C" void kernel_launch(void* const* d_in, const int* in_sizes, int n_in,
                              void* d_out, int out_size)
{
    // metadata order: fushed_features (unused), input_data, W, a, idx
    const float* input = (const float*)d_in[1];
    const float* W     = (const float*)d_in[2];
    const float* a     = (const float*)d_in[3];
    const int*   idx   = (const int*)d_in[4];
    float*       out   = (float*)d_out;

    const int total_warps = NBATCH * NNODE;   // 32768
    const int threads = 256;                  // 8 warps/block
    const int blocks  = total_warps / (threads / 32);  // 4096

    clustering_attention_45286135169491_kernel<<<blocks, threads>>>(
        input, W, a, idx, out);
}